// round 11
// baseline (speedup 1.0000x reference)
#include <cuda_runtime.h>
#include <cuda.h>
#include <cuda_fp16.h>
#include <cstdint>
#include <cstddef>

#define TOKENS 8192
#define DIN    4096
#define DOUT   4096

// ---------------- scratch (allocation-free: device globals) ----------------
__device__ __align__(1024) __half g_A[(size_t)TOKENS * DIN];   // x in fp16, [M,K]
__device__ __align__(1024) __half g_B[(size_t)DOUT * DIN];     // W^T in fp16, [N,K]

// ---------------- helpers (defined before use) ----------------
__device__ __forceinline__ uint32_t h2_as_u32(__half2 h) {
    return *reinterpret_cast<uint32_t*>(&h);
}
__device__ __forceinline__ uint32_t smem_u32(const void* p) {
    uint32_t a;
    asm("{ .reg .u64 t; cvta.to.shared.u64 t, %1; cvt.u32.u64 %0, t; }" : "=r"(a) : "l"(p));
    return a;
}
__device__ __forceinline__ void mbar_init(uint32_t mbar, uint32_t cnt) {
    asm volatile("mbarrier.init.shared.b64 [%0], %1;" :: "r"(mbar), "r"(cnt) : "memory");
}
__device__ __forceinline__ void mbar_arrive(uint32_t mbar) {
    asm volatile("mbarrier.arrive.shared.b64 _, [%0];" :: "r"(mbar) : "memory");
}
__device__ __forceinline__ void mbar_arrive_expect(uint32_t mbar, uint32_t bytes) {
    asm volatile("mbarrier.arrive.expect_tx.shared.b64 _, [%0], %1;" :: "r"(mbar), "r"(bytes) : "memory");
}
__device__ __forceinline__ void mbar_wait(uint32_t mbar, uint32_t parity) {
    asm volatile(
        "{\n\t.reg .pred P;\n\t"
        "WL_%=:\n\t"
        "mbarrier.try_wait.parity.acquire.cta.shared::cta.b64 P, [%0], %1, 0x989680;\n\t"
        "@P bra.uni WD_%=;\n\t"
        "bra.uni WL_%=;\n\t"
        "WD_%=:\n\t}"
        :: "r"(mbar), "r"(parity) : "memory");
}
// non-blocking single probe; acquire on success orders subsequent smem reads
__device__ __forceinline__ uint32_t mbar_test(uint32_t mbar, uint32_t parity) {
    uint32_t ok;
    asm volatile(
        "{\n\t.reg .pred P;\n\t"
        "mbarrier.test_wait.parity.acquire.cta.shared::cta.b64 P, [%1], %2;\n\t"
        "selp.b32 %0, 1, 0, P;\n\t}"
        : "=r"(ok) : "r"(mbar), "r"(parity) : "memory");
    return ok;
}
__device__ __forceinline__ void tma3d(uint32_t dst, const CUtensorMap* map,
                                      int cx, int cy, uint32_t mbar) {
    asm volatile(
        "cp.async.bulk.tensor.3d.shared::cta.global.tile.mbarrier::complete_tx::bytes "
        "[%0], [%1, {%2, %3, %4}], [%5];"
        :: "r"(dst), "l"(map), "r"(cx), "r"(cy), "r"(0), "r"(mbar) : "memory");
}
__device__ __forceinline__ void ldsm4(uint32_t* r, uint32_t addr) {
    asm volatile("ldmatrix.sync.aligned.m8n8.x4.shared.b16 {%0,%1,%2,%3}, [%4];"
                 : "=r"(r[0]), "=r"(r[1]), "=r"(r[2]), "=r"(r[3]) : "r"(addr));
}
__device__ __forceinline__ void mma16816(float* d, const uint32_t* a, const uint32_t* b) {
    asm volatile(
        "mma.sync.aligned.m16n8k16.row.col.f32.f16.f16.f32 "
        "{%0,%1,%2,%3}, {%4,%5,%6,%7}, {%8,%9}, {%0,%1,%2,%3};"
        : "+f"(d[0]), "+f"(d[1]), "+f"(d[2]), "+f"(d[3])
        : "r"(a[0]), "r"(a[1]), "r"(a[2]), "r"(a[3]), "r"(b[0]), "r"(b[1]));
}

// ---------------- merged conversion kernel ----------------
static constexpr int XB = 2048;
static constexpr int WB = 2048;

__global__ void __launch_bounds__(256)
conv_all(const float4* __restrict__ x, const int* __restrict__ W) {
    const int tid = threadIdx.x;
    if (blockIdx.x < XB) {
        uint4* dst = reinterpret_cast<uint4*>(g_A);
        const size_t n4 = (size_t)TOKENS * DIN / 8;
        const size_t stride = (size_t)XB * 256;
        size_t i = (size_t)blockIdx.x * 256 + tid;
#pragma unroll 2
        for (; i < n4; i += stride) {
            float4 v0 = x[2 * i];
            float4 v1 = x[2 * i + 1];
            uint4 o;
            o.x = h2_as_u32(__floats2half2_rn(v0.x, v0.y));
            o.y = h2_as_u32(__floats2half2_rn(v0.z, v0.w));
            o.z = h2_as_u32(__floats2half2_rn(v1.x, v1.y));
            o.w = h2_as_u32(__floats2half2_rn(v1.z, v1.w));
            dst[i] = o;
        }
    } else {
        __shared__ __half t[32][33];
        const int tx = tid & 31;
        const int ty = tid >> 5;
        const int wtiles = (DIN / 32) * (DOUT / 32);
        for (int tt = blockIdx.x - XB; tt < wtiles; tt += WB) {
            int tn = tt & 127, tk = tt >> 7;
            int n0 = tn * 32, k0 = tk * 32;
            __syncthreads();
#pragma unroll
            for (int j = 0; j < 32; j += 8)
                t[ty + j][tx] = __int2half_rn(W[(size_t)(k0 + ty + j) * DOUT + (n0 + tx)]);
            __syncthreads();
#pragma unroll
            for (int j = 0; j < 32; j += 8)
                g_B[(size_t)(n0 + ty + j) * DIN + (k0 + tx)] = t[tx][ty + j];
        }
    }
}

// ---------------- persistent GEMM: CTA 128x256x64, S=4, pipelined barrier probe ----------------
static constexpr int NCTA = 148;
static constexpr int BM = 128, BN = 256, BK = 64;
static constexpr int S = 4;
static constexpr int KT = DIN / BK;                         // 64
static constexpr int NTILES = (TOKENS / BM) * (DOUT / BN);  // 1024
static constexpr uint32_t ABYTES = BM * BK * 2;             // 16384
static constexpr uint32_t BBYTES = BN * BK * 2;             // 32768
static constexpr uint32_t STAGE  = ABYTES + BBYTES;         // 49152
static constexpr uint32_t TXB    = STAGE;
static constexpr uint32_t SMEM_BYTES = S * STAGE + 1024 + 128;

__device__ __forceinline__ void tile_coords(int t, int& m0, int& n0) {
    int grp = t >> 7, r = t & 127;
    m0 = (grp * 8 + (r & 7)) * BM;
    n0 = (r >> 3) * BN;
}

__global__ void __launch_bounds__(256, 1)
gemm_persist(const __grid_constant__ CUtensorMap tmA,
             const __grid_constant__ CUtensorMap tmB,
             float* __restrict__ out) {
    extern __shared__ char smem[];
    const uint32_t sb    = smem_u32(smem);
    const uint32_t tiles = (sb + 1023u) & ~1023u;
    const uint32_t bar   = tiles + S * STAGE;
#define FULL(s)  (bar + (uint32_t)(s) * 16u)
#define EMPTY(s) (bar + (uint32_t)(s) * 16u + 8u)

    const int tid  = threadIdx.x;
    const int lane = tid & 31;
    const int wid  = tid >> 5;
    const int bid  = blockIdx.x;

    if (tid == 0) {
#pragma unroll
        for (int s = 0; s < S; s++) { mbar_init(FULL(s), 1); mbar_init(EMPTY(s), 8); }
    }
    __syncthreads();

    const int ntl   = (NTILES - bid + NCTA - 1) / NCTA;
    const int total = ntl * KT;

    const int wm = wid & 1, wn = wid >> 1;
    const int gq = lane >> 3;
    const uint32_t swz = (uint32_t)(lane & 7) << 4;
    uint32_t offA[4], offB[4];
#pragma unroll
    for (int i = 0; i < 4; i++) {
        int row = wm * 64 + i * 16 + (gq & 1) * 8 + (lane & 7);
        offA[i] = (uint32_t)row * 128u;
    }
#pragma unroll
    for (int j = 0; j < 4; j++) {
        int row = wn * 64 + j * 16 + (gq >> 1) * 8 + (lane & 7);
        offB[j] = ABYTES + (uint32_t)row * 128u;
    }
    const uint32_t selA = (uint32_t)(gq >> 1) * 16u;
    const uint32_t selB = (uint32_t)(gq & 1) * 16u;

    float acc[4][8][4];
#pragma unroll
    for (int i = 0; i < 4; i++)
#pragma unroll
        for (int j = 0; j < 8; j++)
#pragma unroll
            for (int v = 0; v < 4; v++) acc[i][j][v] = 0.f;

    auto fillq = [&](int q) {
        int t = bid + (q >> 6) * NCTA;
        int m0, n0; tile_coords(t, m0, n0);
        int kb = q & (KT - 1);
        int s  = q & (S - 1);
        uint32_t base = tiles + (uint32_t)s * STAGE;
        mbar_arrive_expect(FULL(s), TXB);
        tma3d(base,          &tmA, kb * BK, m0, FULL(s));
        tma3d(base + ABYTES, &tmB, kb * BK, n0, FULL(s));
    };

    if (tid == 0) {
#pragma unroll
        for (int q = 0; q < S - 1; q++) if (q < total) fillq(q);
    }

    uint32_t fullReady = 0;   // stashed probe result for iteration i's FULL wait

#pragma unroll 1
    for (int i = 0; i < total; i++) {
        const int s = i & (S - 1);

        if (tid == 0) {
            const int q = i + S - 1;
            if (q < total) {
                if (q >= S) mbar_wait(EMPTY(q & (S - 1)), ((uint32_t)(q >> 2) + 1u) & 1u);
                fillq(q);
            }
        }

        // skip blocking wait if last iteration's probe already saw this stage full
        if (!fullReady) mbar_wait(FULL(s), (uint32_t)(i >> 2) & 1u);
        const uint32_t base = tiles + (uint32_t)s * STAGE;

#pragma unroll
        for (int ks = 0; ks < 4; ks++) {
            const uint32_t ckA = (((uint32_t)ks * 2u) * 16u + selA) ^ swz;
            const uint32_t ckB = (((uint32_t)ks * 2u) * 16u + selB) ^ swz;
            uint32_t a[4][4], b[4][4];
#pragma unroll
            for (int ii = 0; ii < 4; ii++) ldsm4(a[ii], base + offA[ii] + ckA);
#pragma unroll
            for (int jj = 0; jj < 4; jj++) ldsm4(b[jj], base + offB[jj] + ckB);
#pragma unroll
            for (int ii = 0; ii < 4; ii++)
#pragma unroll
                for (int jj = 0; jj < 4; jj++) {
                    mma16816(acc[ii][2 * jj],     a[ii], &b[jj][0]);
                    mma16816(acc[ii][2 * jj + 1], a[ii], &b[jj][2]);
                }
            // pipelined probe for the NEXT iteration's FULL barrier; latency
            // hidden under the remaining 3 ks-blocks of HMMAs
            if (ks == 0) {
                const int inext = i + 1;
                if (inext < total)
                    fullReady = mbar_test(FULL(inext & (S - 1)),
                                          (uint32_t)(inext >> 2) & 1u);
            }
        }
        if (lane == 0) mbar_arrive(EMPTY(s));

        if ((i & (KT - 1)) == KT - 1) {
            int t = bid + (i >> 6) * NCTA;
            int m0, n0; tile_coords(t, m0, n0);
            const int mrow = m0 + wm * 64 + (lane >> 2);
            const int ncol = n0 + wn * 64 + (lane & 3) * 2;
#pragma unroll
            for (int ii = 0; ii < 4; ii++) {
#pragma unroll
                for (int jn = 0; jn < 8; jn++) {
                    float2 v0 = make_float2(acc[ii][jn][0], acc[ii][jn][1]);
                    float2 v1 = make_float2(acc[ii][jn][2], acc[ii][jn][3]);
                    *reinterpret_cast<float2*>(out + (size_t)(mrow + ii * 16) * DOUT + ncol + jn * 8)     = v0;
                    *reinterpret_cast<float2*>(out + (size_t)(mrow + ii * 16 + 8) * DOUT + ncol + jn * 8) = v1;
#pragma unroll
                    for (int v = 0; v < 4; v++) acc[ii][jn][v] = 0.f;
                }
            }
        }
    }
#undef FULL
#undef EMPTY
}

// ---------------- host launch ----------------
typedef CUresult (*encode_fn_t)(CUtensorMap*, CUtensorMapDataType, cuuint32_t, void*,
                                const cuuint64_t*, const cuuint64_t*, const cuuint32_t*,
                                const cuuint32_t*, CUtensorMapInterleave, CUtensorMapSwizzle,
                                CUtensorMapL2promotion, CUtensorMapFloatOOBfill);

extern "C" void kernel_launch(void* const* d_in, const int* in_sizes, int n_in,
                              void* d_out, int out_size) {
    const float* x = (const float*)d_in[0];
    const int*   W = (const int*)d_in[1];
    float* out = (float*)d_out;

    void* pa = nullptr; void* pb = nullptr;
    cudaGetSymbolAddress(&pa, g_A);
    cudaGetSymbolAddress(&pb, g_B);

    static encode_fn_t enc = nullptr;
    if (!enc) {
        cudaDriverEntryPointQueryResult st;
        cudaGetDriverEntryPointByVersion("cuTensorMapEncodeTiled", (void**)&enc,
                                         12000, cudaEnableDefault, &st);
    }
    CUtensorMap mA{}, mB{};
    {
        cuuint64_t dims[3] = {DIN, TOKENS, 1};
        cuuint64_t str[2]  = {DIN * 2ull, (cuuint64_t)TOKENS * DIN * 2ull};
        cuuint32_t box[3]  = {64, 128, 1};
        cuuint32_t es[3]   = {1, 1, 1};
        enc(&mA, CU_TENSOR_MAP_DATA_TYPE_FLOAT16, 3, pa, dims, str, box, es,
            CU_TENSOR_MAP_INTERLEAVE_NONE, CU_TENSOR_MAP_SWIZZLE_128B,
            CU_TENSOR_MAP_L2_PROMOTION_L2_128B, CU_TENSOR_MAP_FLOAT_OOB_FILL_NONE);
    }
    {
        cuuint64_t dims[3] = {DIN, DOUT, 1};
        cuuint64_t str[2]  = {DIN * 2ull, (cuuint64_t)DOUT * DIN * 2ull};
        cuuint32_t box[3]  = {64, 256, 1};
        cuuint32_t es[3]   = {1, 1, 1};
        enc(&mB, CU_TENSOR_MAP_DATA_TYPE_FLOAT16, 3, pb, dims, str, box, es,
            CU_TENSOR_MAP_INTERLEAVE_NONE, CU_TENSOR_MAP_SWIZZLE_128B,
            CU_TENSOR_MAP_L2_PROMOTION_L2_128B, CU_TENSOR_MAP_FLOAT_OOB_FILL_NONE);
    }

    conv_all<<<XB + WB, 256>>>((const float4*)x, W);

    cudaFuncSetAttribute(gemm_persist, cudaFuncAttributeMaxDynamicSharedMemorySize, SMEM_BYTES);
    gemm_persist<<<NCTA, 256, SMEM_BYTES>>>(mA, mB, out);
}

// round 12
// speedup vs baseline: 1.0061x; 1.0061x over previous
#include <cuda_runtime.h>
#include <cuda.h>
#include <cuda_fp16.h>
#include <cstdint>
#include <cstddef>

#define TOKENS 8192
#define DIN    4096
#define DOUT   4096

// ---------------- scratch (allocation-free: device globals) ----------------
__device__ __align__(1024) __half g_A[(size_t)TOKENS * DIN];   // x in fp16, [M,K]
__device__ __align__(1024) __half g_B[(size_t)DOUT * DIN];     // W^T in fp16, [N,K]

// ---------------- helpers (defined before use) ----------------
__device__ __forceinline__ uint32_t h2_as_u32(__half2 h) {
    return *reinterpret_cast<uint32_t*>(&h);
}
__device__ __forceinline__ uint32_t smem_u32(const void* p) {
    uint32_t a;
    asm("{ .reg .u64 t; cvta.to.shared.u64 t, %1; cvt.u32.u64 %0, t; }" : "=r"(a) : "l"(p));
    return a;
}
__device__ __forceinline__ void mbar_init(uint32_t mbar, uint32_t cnt) {
    asm volatile("mbarrier.init.shared.b64 [%0], %1;" :: "r"(mbar), "r"(cnt) : "memory");
}
__device__ __forceinline__ void mbar_arrive(uint32_t mbar) {
    asm volatile("mbarrier.arrive.shared.b64 _, [%0];" :: "r"(mbar) : "memory");
}
__device__ __forceinline__ void mbar_arrive_expect(uint32_t mbar, uint32_t bytes) {
    asm volatile("mbarrier.arrive.expect_tx.shared.b64 _, [%0], %1;" :: "r"(mbar), "r"(bytes) : "memory");
}
__device__ __forceinline__ void mbar_wait(uint32_t mbar, uint32_t parity) {
    asm volatile(
        "{\n\t.reg .pred P;\n\t"
        "WL_%=:\n\t"
        "mbarrier.try_wait.parity.acquire.cta.shared::cta.b64 P, [%0], %1, 0x989680;\n\t"
        "@P bra.uni WD_%=;\n\t"
        "bra.uni WL_%=;\n\t"
        "WD_%=:\n\t}"
        :: "r"(mbar), "r"(parity) : "memory");
}
__device__ __forceinline__ void tma3d(uint32_t dst, const CUtensorMap* map,
                                      int cx, int cy, uint32_t mbar) {
    asm volatile(
        "cp.async.bulk.tensor.3d.shared::cta.global.tile.mbarrier::complete_tx::bytes "
        "[%0], [%1, {%2, %3, %4}], [%5];"
        :: "r"(dst), "l"(map), "r"(cx), "r"(cy), "r"(0), "r"(mbar) : "memory");
}
__device__ __forceinline__ void ldsm4(uint32_t* r, uint32_t addr) {
    asm volatile("ldmatrix.sync.aligned.m8n8.x4.shared.b16 {%0,%1,%2,%3}, [%4];"
                 : "=r"(r[0]), "=r"(r[1]), "=r"(r[2]), "=r"(r[3]) : "r"(addr));
}
__device__ __forceinline__ void mma16816(float* d, const uint32_t* a, const uint32_t* b) {
    asm volatile(
        "mma.sync.aligned.m16n8k16.row.col.f32.f16.f16.f32 "
        "{%0,%1,%2,%3}, {%4,%5,%6,%7}, {%8,%9}, {%0,%1,%2,%3};"
        : "+f"(d[0]), "+f"(d[1]), "+f"(d[2]), "+f"(d[3])
        : "r"(a[0]), "r"(a[1]), "r"(a[2]), "r"(a[3]), "r"(b[0]), "r"(b[1]));
}

// ---------------- merged conversion kernel ----------------
static constexpr int XB = 2048;
static constexpr int WB = 2048;

__global__ void __launch_bounds__(256)
conv_all(const float4* __restrict__ x, const int* __restrict__ W) {
    const int tid = threadIdx.x;
    if (blockIdx.x < XB) {
        uint4* dst = reinterpret_cast<uint4*>(g_A);
        const size_t n4 = (size_t)TOKENS * DIN / 8;
        const size_t stride = (size_t)XB * 256;
        size_t i = (size_t)blockIdx.x * 256 + tid;
#pragma unroll 2
        for (; i < n4; i += stride) {
            float4 v0 = x[2 * i];
            float4 v1 = x[2 * i + 1];
            uint4 o;
            o.x = h2_as_u32(__floats2half2_rn(v0.x, v0.y));
            o.y = h2_as_u32(__floats2half2_rn(v0.z, v0.w));
            o.z = h2_as_u32(__floats2half2_rn(v1.x, v1.y));
            o.w = h2_as_u32(__floats2half2_rn(v1.z, v1.w));
            dst[i] = o;
        }
    } else {
        __shared__ __half t[32][33];
        const int tx = tid & 31;
        const int ty = tid >> 5;
        const int wtiles = (DIN / 32) * (DOUT / 32);
        for (int tt = blockIdx.x - XB; tt < wtiles; tt += WB) {
            int tn = tt & 127, tk = tt >> 7;
            int n0 = tn * 32, k0 = tk * 32;
            __syncthreads();
#pragma unroll
            for (int j = 0; j < 32; j += 8)
                t[ty + j][tx] = __int2half_rn(W[(size_t)(k0 + ty + j) * DOUT + (n0 + tx)]);
            __syncthreads();
#pragma unroll
            for (int j = 0; j < 32; j += 8)
                g_B[(size_t)(n0 + ty + j) * DIN + (k0 + tx)] = t[tx][ty + j];
        }
    }
}

// ---------------- persistent GEMM: CTA 128x128x64, 4 warps, 2 CTAs/SM, S=3 ----------------
static constexpr int NCTA = 296;                            // 2 per SM
static constexpr int BM = 128, BN = 128, BK = 64;
static constexpr int S = 3;
static constexpr int KT = DIN / BK;                         // 64
static constexpr int NTILES = (TOKENS / BM) * (DOUT / BN);  // 2048
static constexpr uint32_t ABYTES = BM * BK * 2;             // 16384
static constexpr uint32_t BBYTES = BN * BK * 2;             // 16384
static constexpr uint32_t STAGE  = ABYTES + BBYTES;         // 32768
static constexpr uint32_t TXB    = STAGE;
static constexpr uint32_t SMEM_BYTES = S * STAGE + 1024 + 128;  // ~99.5 KB -> 2 CTAs/SM

__device__ __forceinline__ void tile_coords(int t, int& m0, int& n0) {
    int grp = t >> 8, r = t & 255;       // 8 m-tiles x 32 n-tiles per group
    m0 = (grp * 8 + (r & 7)) * BM;
    n0 = (r >> 3) * BN;
}

__global__ void __launch_bounds__(128, 2)
gemm_persist(const __grid_constant__ CUtensorMap tmA,
             const __grid_constant__ CUtensorMap tmB,
             float* __restrict__ out) {
    extern __shared__ char smem[];
    const uint32_t sb    = smem_u32(smem);
    const uint32_t tiles = (sb + 1023u) & ~1023u;
    const uint32_t bar   = tiles + S * STAGE;
#define FULL(s)  (bar + (uint32_t)(s) * 16u)
#define EMPTY(s) (bar + (uint32_t)(s) * 16u + 8u)

    const int tid  = threadIdx.x;
    const int lane = tid & 31;
    const int wid  = tid >> 5;           // 0..3
    const int bid  = blockIdx.x;

    if (tid == 0) {
#pragma unroll
        for (int s = 0; s < S; s++) { mbar_init(FULL(s), 1); mbar_init(EMPTY(s), 4); }
    }
    __syncthreads();

    const int ntl   = (NTILES - bid + NCTA - 1) / NCTA;
    const int total = ntl * KT;

    // warp grid 2m x 2n, warp tile 64x64
    const int wm = wid & 1, wn = wid >> 1;
    const int gq = lane >> 3;
    const uint32_t swz = (uint32_t)(lane & 7) << 4;
    uint32_t offA[4], offB[4];
#pragma unroll
    for (int i = 0; i < 4; i++) {
        int row = wm * 64 + i * 16 + (gq & 1) * 8 + (lane & 7);
        offA[i] = (uint32_t)row * 128u;
    }
#pragma unroll
    for (int j = 0; j < 4; j++) {
        int row = wn * 64 + j * 16 + (gq >> 1) * 8 + (lane & 7);
        offB[j] = ABYTES + (uint32_t)row * 128u;
    }
    const uint32_t selA = (uint32_t)(gq >> 1) * 16u;
    const uint32_t selB = (uint32_t)(gq & 1) * 16u;

    float acc[4][8][4];
#pragma unroll
    for (int i = 0; i < 4; i++)
#pragma unroll
        for (int j = 0; j < 8; j++)
#pragma unroll
            for (int v = 0; v < 4; v++) acc[i][j][v] = 0.f;

    // producer cursor over fills (fresh-barrier trick: first S EMPTY-waits pass)
    int ps = 0, pph = 1;
    auto fillq = [&](int q) {
        mbar_wait(EMPTY(ps), (uint32_t)pph);
        int t = bid + (q >> 6) * NCTA;
        int m0, n0; tile_coords(t, m0, n0);
        int kb = q & (KT - 1);
        uint32_t base = tiles + (uint32_t)ps * STAGE;
        mbar_arrive_expect(FULL(ps), TXB);
        tma3d(base,          &tmA, kb * BK, m0, FULL(ps));
        tma3d(base + ABYTES, &tmB, kb * BK, n0, FULL(ps));
        if (++ps == S) { ps = 0; pph ^= 1; }
    };

    if (tid == 0) {
#pragma unroll
        for (int q = 0; q < S - 1; q++) if (q < total) fillq(q);
    }

    int cs = 0, cph = 0;   // consumer cursor

#pragma unroll 1
    for (int i = 0; i < total; i++) {
        if (tid == 0) {
            const int q = i + S - 1;
            if (q < total) fillq(q);
        }

        mbar_wait(FULL(cs), (uint32_t)cph);
        const uint32_t base = tiles + (uint32_t)cs * STAGE;

#pragma unroll
        for (int ks = 0; ks < 4; ks++) {
            const uint32_t ckA = (((uint32_t)ks * 2u) * 16u + selA) ^ swz;
            const uint32_t ckB = (((uint32_t)ks * 2u) * 16u + selB) ^ swz;
            uint32_t a[4][4], b[4][4];
#pragma unroll
            for (int ii = 0; ii < 4; ii++) ldsm4(a[ii], base + offA[ii] + ckA);
#pragma unroll
            for (int jj = 0; jj < 4; jj++) ldsm4(b[jj], base + offB[jj] + ckB);
#pragma unroll
            for (int ii = 0; ii < 4; ii++)
#pragma unroll
                for (int jj = 0; jj < 4; jj++) {
                    mma16816(acc[ii][2 * jj],     a[ii], &b[jj][0]);
                    mma16816(acc[ii][2 * jj + 1], a[ii], &b[jj][2]);
                }
        }
        if (lane == 0) mbar_arrive(EMPTY(cs));
        if (++cs == S) { cs = 0; cph ^= 1; }

        if ((i & (KT - 1)) == KT - 1) {
            int t = bid + (i >> 6) * NCTA;
            int m0, n0; tile_coords(t, m0, n0);
            const int mrow = m0 + wm * 64 + (lane >> 2);
            const int ncol = n0 + wn * 64 + (lane & 3) * 2;
#pragma unroll
            for (int ii = 0; ii < 4; ii++) {
#pragma unroll
                for (int jn = 0; jn < 8; jn++) {
                    float2 v0 = make_float2(acc[ii][jn][0], acc[ii][jn][1]);
                    float2 v1 = make_float2(acc[ii][jn][2], acc[ii][jn][3]);
                    *reinterpret_cast<float2*>(out + (size_t)(mrow + ii * 16) * DOUT + ncol + jn * 8)     = v0;
                    *reinterpret_cast<float2*>(out + (size_t)(mrow + ii * 16 + 8) * DOUT + ncol + jn * 8) = v1;
#pragma unroll
                    for (int v = 0; v < 4; v++) acc[ii][jn][v] = 0.f;
                }
            }
        }
    }
#undef FULL
#undef EMPTY
}

// ---------------- host launch ----------------
typedef CUresult (*encode_fn_t)(CUtensorMap*, CUtensorMapDataType, cuuint32_t, void*,
                                const cuuint64_t*, const cuuint64_t*, const cuuint32_t*,
                                const cuuint32_t*, CUtensorMapInterleave, CUtensorMapSwizzle,
                                CUtensorMapL2promotion, CUtensorMapFloatOOBfill);

extern "C" void kernel_launch(void* const* d_in, const int* in_sizes, int n_in,
                              void* d_out, int out_size) {
    const float* x = (const float*)d_in[0];
    const int*   W = (const int*)d_in[1];
    float* out = (float*)d_out;

    void* pa = nullptr; void* pb = nullptr;
    cudaGetSymbolAddress(&pa, g_A);
    cudaGetSymbolAddress(&pb, g_B);

    static encode_fn_t enc = nullptr;
    if (!enc) {
        cudaDriverEntryPointQueryResult st;
        cudaGetDriverEntryPointByVersion("cuTensorMapEncodeTiled", (void**)&enc,
                                         12000, cudaEnableDefault, &st);
    }
    CUtensorMap mA{}, mB{};
    {
        cuuint64_t dims[3] = {DIN, TOKENS, 1};
        cuuint64_t str[2]  = {DIN * 2ull, (cuuint64_t)TOKENS * DIN * 2ull};
        cuuint32_t box[3]  = {64, 128, 1};
        cuuint32_t es[3]   = {1, 1, 1};
        enc(&mA, CU_TENSOR_MAP_DATA_TYPE_FLOAT16, 3, pa, dims, str, box, es,
            CU_TENSOR_MAP_INTERLEAVE_NONE, CU_TENSOR_MAP_SWIZZLE_128B,
            CU_TENSOR_MAP_L2_PROMOTION_L2_128B, CU_TENSOR_MAP_FLOAT_OOB_FILL_NONE);
    }
    {
        cuuint64_t dims[3] = {DIN, DOUT, 1};
        cuuint64_t str[2]  = {DIN * 2ull, (cuuint64_t)DOUT * DIN * 2ull};
        cuuint32_t box[3]  = {64, 128, 1};
        cuuint32_t es[3]   = {1, 1, 1};
        enc(&mB, CU_TENSOR_MAP_DATA_TYPE_FLOAT16, 3, pb, dims, str, box, es,
            CU_TENSOR_MAP_INTERLEAVE_NONE, CU_TENSOR_MAP_SWIZZLE_128B,
            CU_TENSOR_MAP_L2_PROMOTION_L2_128B, CU_TENSOR_MAP_FLOAT_OOB_FILL_NONE);
    }

    conv_all<<<XB + WB, 256>>>((const float4*)x, W);

    cudaFuncSetAttribute(gemm_persist, cudaFuncAttributeMaxDynamicSharedMemorySize, SMEM_BYTES);
    gemm_persist<<<NCTA, 128, SMEM_BYTES>>>(mA, mB, out);
}

// round 13
// speedup vs baseline: 1.0788x; 1.0722x over previous
#include <cuda_runtime.h>
#include <cuda.h>
#include <cuda_fp16.h>
#include <cstdint>
#include <cstddef>

#define TOKENS 8192
#define DIN    4096
#define DOUT   4096

// ---------------- scratch (allocation-free: device globals) ----------------
__device__ __align__(1024) __half g_A[(size_t)TOKENS * DIN];   // x in fp16, [M,K]
__device__ __align__(1024) __half g_B[(size_t)DOUT * DIN];     // W^T in fp16, [N,K]

// ---------------- helpers (defined before use) ----------------
__device__ __forceinline__ uint32_t h2_as_u32(__half2 h) {
    return *reinterpret_cast<uint32_t*>(&h);
}
__device__ __forceinline__ uint32_t smem_u32(const void* p) {
    uint32_t a;
    asm("{ .reg .u64 t; cvta.to.shared.u64 t, %1; cvt.u32.u64 %0, t; }" : "=r"(a) : "l"(p));
    return a;
}
__device__ __forceinline__ void mbar_init(uint32_t mbar, uint32_t cnt) {
    asm volatile("mbarrier.init.shared.b64 [%0], %1;" :: "r"(mbar), "r"(cnt) : "memory");
}
__device__ __forceinline__ void mbar_arrive(uint32_t mbar) {
    asm volatile("mbarrier.arrive.shared.b64 _, [%0];" :: "r"(mbar) : "memory");
}
__device__ __forceinline__ void mbar_arrive_expect(uint32_t mbar, uint32_t bytes) {
    asm volatile("mbarrier.arrive.expect_tx.shared.b64 _, [%0], %1;" :: "r"(mbar), "r"(bytes) : "memory");
}
__device__ __forceinline__ void mbar_wait(uint32_t mbar, uint32_t parity) {
    asm volatile(
        "{\n\t.reg .pred P;\n\t"
        "WL_%=:\n\t"
        "mbarrier.try_wait.parity.acquire.cta.shared::cta.b64 P, [%0], %1, 0x989680;\n\t"
        "@P bra.uni WD_%=;\n\t"
        "bra.uni WL_%=;\n\t"
        "WD_%=:\n\t}"
        :: "r"(mbar), "r"(parity) : "memory");
}
__device__ __forceinline__ void tma3d(uint32_t dst, const CUtensorMap* map,
                                      int cx, int cy, uint32_t mbar) {
    asm volatile(
        "cp.async.bulk.tensor.3d.shared::cta.global.tile.mbarrier::complete_tx::bytes "
        "[%0], [%1, {%2, %3, %4}], [%5];"
        :: "r"(dst), "l"(map), "r"(cx), "r"(cy), "r"(0), "r"(mbar) : "memory");
}
__device__ __forceinline__ void ldsm4(uint32_t* r, uint32_t addr) {
    asm volatile("ldmatrix.sync.aligned.m8n8.x4.shared.b16 {%0,%1,%2,%3}, [%4];"
                 : "=r"(r[0]), "=r"(r[1]), "=r"(r[2]), "=r"(r[3]) : "r"(addr));
}
__device__ __forceinline__ void mma16816(float* d, const uint32_t* a, const uint32_t* b) {
    asm volatile(
        "mma.sync.aligned.m16n8k16.row.col.f32.f16.f16.f32 "
        "{%0,%1,%2,%3}, {%4,%5,%6,%7}, {%8,%9}, {%0,%1,%2,%3};"
        : "+f"(d[0]), "+f"(d[1]), "+f"(d[2]), "+f"(d[3])
        : "r"(a[0]), "r"(a[1]), "r"(a[2]), "r"(a[3]), "r"(b[0]), "r"(b[1]));
}

// ---------------- merged conversion kernel ----------------
// x and W are read-once: stream them through L2 (__ldcs) so the A/B writes
// (read soon by the GEMM) keep L2 residency.
static constexpr int XB = 2048;
static constexpr int WB = 2048;

__global__ void __launch_bounds__(256)
conv_all(const float4* __restrict__ x, const int* __restrict__ W) {
    const int tid = threadIdx.x;
    if (blockIdx.x < XB) {
        uint4* dst = reinterpret_cast<uint4*>(g_A);
        const size_t n4 = (size_t)TOKENS * DIN / 8;
        const size_t stride = (size_t)XB * 256;
        size_t i = (size_t)blockIdx.x * 256 + tid;
#pragma unroll 2
        for (; i < n4; i += stride) {
            float4 v0 = __ldcs(&x[2 * i]);
            float4 v1 = __ldcs(&x[2 * i + 1]);
            uint4 o;
            o.x = h2_as_u32(__floats2half2_rn(v0.x, v0.y));
            o.y = h2_as_u32(__floats2half2_rn(v0.z, v0.w));
            o.z = h2_as_u32(__floats2half2_rn(v1.x, v1.y));
            o.w = h2_as_u32(__floats2half2_rn(v1.z, v1.w));
            dst[i] = o;
        }
    } else {
        __shared__ __half t[32][33];
        const int tx = tid & 31;
        const int ty = tid >> 5;
        const int wtiles = (DIN / 32) * (DOUT / 32);
        for (int tt = blockIdx.x - XB; tt < wtiles; tt += WB) {
            int tn = tt & 127, tk = tt >> 7;
            int n0 = tn * 32, k0 = tk * 32;
            __syncthreads();
#pragma unroll
            for (int j = 0; j < 32; j += 8)
                t[ty + j][tx] = __int2half_rn(__ldcs(&W[(size_t)(k0 + ty + j) * DOUT + (n0 + tx)]));
            __syncthreads();
#pragma unroll
            for (int j = 0; j < 32; j += 8)
                g_B[(size_t)(n0 + ty + j) * DIN + (k0 + tx)] = t[tx][ty + j];
        }
    }
}

// ---------------- persistent GEMM: CTA 128x256x64, S=4 (proven best config) ----------------
static constexpr int NCTA = 148;
static constexpr int BM = 128, BN = 256, BK = 64;
static constexpr int S = 4;
static constexpr int KT = DIN / BK;                         // 64
static constexpr int NTILES = (TOKENS / BM) * (DOUT / BN);  // 1024
static constexpr uint32_t ABYTES = BM * BK * 2;             // 16384
static constexpr uint32_t BBYTES = BN * BK * 2;             // 32768
static constexpr uint32_t STAGE  = ABYTES + BBYTES;         // 49152
static constexpr uint32_t TXB    = STAGE;
static constexpr uint32_t SMEM_BYTES = S * STAGE + 1024 + 128;

__device__ __forceinline__ void tile_coords(int t, int& m0, int& n0) {
    int grp = t >> 7, r = t & 127;
    m0 = (grp * 8 + (r & 7)) * BM;
    n0 = (r >> 3) * BN;
}

__global__ void __launch_bounds__(256, 1)
gemm_persist(const __grid_constant__ CUtensorMap tmA,
             const __grid_constant__ CUtensorMap tmB,
             float* __restrict__ out) {
    extern __shared__ char smem[];
    const uint32_t sb    = smem_u32(smem);
    const uint32_t tiles = (sb + 1023u) & ~1023u;
    const uint32_t bar   = tiles + S * STAGE;
#define FULL(s)  (bar + (uint32_t)(s) * 16u)
#define EMPTY(s) (bar + (uint32_t)(s) * 16u + 8u)

    const int tid  = threadIdx.x;
    const int lane = tid & 31;
    const int wid  = tid >> 5;
    const int bid  = blockIdx.x;

    if (tid == 0) {
#pragma unroll
        for (int s = 0; s < S; s++) { mbar_init(FULL(s), 1); mbar_init(EMPTY(s), 8); }
    }
    __syncthreads();

    const int ntl   = (NTILES - bid + NCTA - 1) / NCTA;
    const int total = ntl * KT;

    const int wm = wid & 1, wn = wid >> 1;
    const int gq = lane >> 3;
    const uint32_t swz = (uint32_t)(lane & 7) << 4;
    uint32_t offA[4], offB[4];
#pragma unroll
    for (int i = 0; i < 4; i++) {
        int row = wm * 64 + i * 16 + (gq & 1) * 8 + (lane & 7);
        offA[i] = (uint32_t)row * 128u;
    }
#pragma unroll
    for (int j = 0; j < 4; j++) {
        int row = wn * 64 + j * 16 + (gq >> 1) * 8 + (lane & 7);
        offB[j] = ABYTES + (uint32_t)row * 128u;
    }
    const uint32_t selA = (uint32_t)(gq >> 1) * 16u;
    const uint32_t selB = (uint32_t)(gq & 1) * 16u;

    float acc[4][8][4];
#pragma unroll
    for (int i = 0; i < 4; i++)
#pragma unroll
        for (int j = 0; j < 8; j++)
#pragma unroll
            for (int v = 0; v < 4; v++) acc[i][j][v] = 0.f;

    auto fillq = [&](int q) {
        int t = bid + (q >> 6) * NCTA;
        int m0, n0; tile_coords(t, m0, n0);
        int kb = q & (KT - 1);
        int s  = q & (S - 1);
        uint32_t base = tiles + (uint32_t)s * STAGE;
        mbar_arrive_expect(FULL(s), TXB);
        tma3d(base,          &tmA, kb * BK, m0, FULL(s));
        tma3d(base + ABYTES, &tmB, kb * BK, n0, FULL(s));
    };

    if (tid == 0) {
#pragma unroll
        for (int q = 0; q < S - 1; q++) if (q < total) fillq(q);
    }

#pragma unroll 1
    for (int i = 0; i < total; i++) {
        const int s = i & (S - 1);

        if (tid == 0) {
            const int q = i + S - 1;
            if (q < total) {
                if (q >= S) mbar_wait(EMPTY(q & (S - 1)), ((uint32_t)(q >> 2) + 1u) & 1u);
                fillq(q);
            }
        }

        mbar_wait(FULL(s), (uint32_t)(i >> 2) & 1u);
        const uint32_t base = tiles + (uint32_t)s * STAGE;

#pragma unroll
        for (int ks = 0; ks < 4; ks++) {
            const uint32_t ckA = (((uint32_t)ks * 2u) * 16u + selA) ^ swz;
            const uint32_t ckB = (((uint32_t)ks * 2u) * 16u + selB) ^ swz;
            uint32_t a[4][4], b[4][4];
#pragma unroll
            for (int ii = 0; ii < 4; ii++) ldsm4(a[ii], base + offA[ii] + ckA);
#pragma unroll
            for (int jj = 0; jj < 4; jj++) ldsm4(b[jj], base + offB[jj] + ckB);
#pragma unroll
            for (int ii = 0; ii < 4; ii++)
#pragma unroll
                for (int jj = 0; jj < 4; jj++) {
                    mma16816(acc[ii][2 * jj],     a[ii], &b[jj][0]);
                    mma16816(acc[ii][2 * jj + 1], a[ii], &b[jj][2]);
                }
        }
        if (lane == 0) mbar_arrive(EMPTY(s));

        if ((i & (KT - 1)) == KT - 1) {
            int t = bid + (i >> 6) * NCTA;
            int m0, n0; tile_coords(t, m0, n0);
            const int mrow = m0 + wm * 64 + (lane >> 2);
            const int ncol = n0 + wn * 64 + (lane & 3) * 2;
#pragma unroll
            for (int ii = 0; ii < 4; ii++) {
#pragma unroll
                for (int jn = 0; jn < 8; jn++) {
                    float2 v0 = make_float2(acc[ii][jn][0], acc[ii][jn][1]);
                    float2 v1 = make_float2(acc[ii][jn][2], acc[ii][jn][3]);
                    *reinterpret_cast<float2*>(out + (size_t)(mrow + ii * 16) * DOUT + ncol + jn * 8)     = v0;
                    *reinterpret_cast<float2*>(out + (size_t)(mrow + ii * 16 + 8) * DOUT + ncol + jn * 8) = v1;
#pragma unroll
                    for (int v = 0; v < 4; v++) acc[ii][jn][v] = 0.f;
                }
            }
        }
    }
#undef FULL
#undef EMPTY
}

// ---------------- host launch ----------------
typedef CUresult (*encode_fn_t)(CUtensorMap*, CUtensorMapDataType, cuuint32_t, void*,
                                const cuuint64_t*, const cuuint64_t*, const cuuint32_t*,
                                const cuuint32_t*, CUtensorMapInterleave, CUtensorMapSwizzle,
                                CUtensorMapL2promotion, CUtensorMapFloatOOBfill);

extern "C" void kernel_launch(void* const* d_in, const int* in_sizes, int n_in,
                              void* d_out, int out_size) {
    const float* x = (const float*)d_in[0];
    const int*   W = (const int*)d_in[1];
    float* out = (float*)d_out;

    void* pa = nullptr; void* pb = nullptr;
    cudaGetSymbolAddress(&pa, g_A);
    cudaGetSymbolAddress(&pb, g_B);

    static encode_fn_t enc = nullptr;
    if (!enc) {
        cudaDriverEntryPointQueryResult st;
        cudaGetDriverEntryPointByVersion("cuTensorMapEncodeTiled", (void**)&enc,
                                         12000, cudaEnableDefault, &st);
    }
    CUtensorMap mA{}, mB{};
    {
        cuuint64_t dims[3] = {DIN, TOKENS, 1};
        cuuint64_t str[2]  = {DIN * 2ull, (cuuint64_t)TOKENS * DIN * 2ull};
        cuuint32_t box[3]  = {64, 128, 1};
        cuuint32_t es[3]   = {1, 1, 1};
        enc(&mA, CU_TENSOR_MAP_DATA_TYPE_FLOAT16, 3, pa, dims, str, box, es,
            CU_TENSOR_MAP_INTERLEAVE_NONE, CU_TENSOR_MAP_SWIZZLE_128B,
            CU_TENSOR_MAP_L2_PROMOTION_L2_128B, CU_TENSOR_MAP_FLOAT_OOB_FILL_NONE);
    }
    {
        cuuint64_t dims[3] = {DIN, DOUT, 1};
        cuuint64_t str[2]  = {DIN * 2ull, (cuuint64_t)DOUT * DIN * 2ull};
        cuuint32_t box[3]  = {64, 256, 1};
        cuuint32_t es[3]   = {1, 1, 1};
        enc(&mB, CU_TENSOR_MAP_DATA_TYPE_FLOAT16, 3, pb, dims, str, box, es,
            CU_TENSOR_MAP_INTERLEAVE_NONE, CU_TENSOR_MAP_SWIZZLE_128B,
            CU_TENSOR_MAP_L2_PROMOTION_L2_128B, CU_TENSOR_MAP_FLOAT_OOB_FILL_NONE);
    }

    conv_all<<<XB + WB, 256>>>((const float4*)x, W);

    cudaFuncSetAttribute(gemm_persist, cudaFuncAttributeMaxDynamicSharedMemorySize, SMEM_BYTES);
    gemm_persist<<<NCTA, 256, SMEM_BYTES>>>(mA, mB, out);
}